// round 16
// baseline (speedup 1.0000x reference)
#include <cuda_runtime.h>
#include <math.h>

// Problem dims
#define NB   2
#define NT   2048
#define NHID 2048
#define NH   16
#define NKVH 4
#define ND   128
#define NM   (NB*NT)      // 4096 rows

// Scratch (device globals: allocation-free)
__device__ float g_Q[(size_t)NB*NH*NT*ND];    // [B,H,T,D]   32MB
__device__ float g_K[(size_t)NB*NKVH*NT*ND];  // [B,KVH,T,D]  8MB
__device__ float g_V[(size_t)NB*NKVH*NT*ND];  //              8MB
__device__ float g_A[(size_t)NB*NT*NH*ND];    // attn out [B,T,H*D] 32MB

// ---------------------------------------------------------------------------
// SGEMM core: 128x128 tile, K-step 16, 256 threads, 8x8 micro-tile
// ---------------------------------------------------------------------------
#define BM 128
#define BN 128
#define BK 16
#define SA_STRIDE 132   // padded to break store bank conflicts

__device__ __forceinline__ void gemm128(const float* __restrict__ A, int lda,
                                        const float* __restrict__ Bm, int ldb,
                                        int K, float acc[8][8])
{
    __shared__ float sA[BK * SA_STRIDE];   // transposed: sA[k][m]
    __shared__ float sB[BK * BN];          // sB[k][n]
    const int tid = threadIdx.x;
    const int rowbase = (tid >> 4) << 3;
    const int colbase = (tid & 15) << 3;

#pragma unroll
    for (int i = 0; i < 8; i++)
#pragma unroll
        for (int j = 0; j < 8; j++) acc[i][j] = 0.0f;

    for (int kt = 0; kt < K; kt += BK) {
        // Load A tile (128x16) transposed into sA
#pragma unroll
        for (int t = 0; t < 2; t++) {
            int i = tid * 2 + t;              // 0..511 float4s
            int r  = i >> 2;                  // row 0..127
            int cg = (i & 3) << 2;            // col 0,4,8,12
            float4 v = *(const float4*)(A + (size_t)r * lda + kt + cg);
            sA[(cg + 0) * SA_STRIDE + r] = v.x;
            sA[(cg + 1) * SA_STRIDE + r] = v.y;
            sA[(cg + 2) * SA_STRIDE + r] = v.z;
            sA[(cg + 3) * SA_STRIDE + r] = v.w;
        }
        // Load B tile (16x128)
#pragma unroll
        for (int t = 0; t < 2; t++) {
            int i = tid * 2 + t;
            int r = i >> 5;                   // row 0..15
            int c = (i & 31) << 2;            // col 0..124
            *(float4*)&sB[r * BN + c] =
                *(const float4*)(Bm + (size_t)(kt + r) * ldb + c);
        }
        __syncthreads();

#pragma unroll
        for (int kk = 0; kk < BK; kk++) {
            float a[8], b[8];
            *(float4*)&a[0] = *(float4*)&sA[kk * SA_STRIDE + rowbase];
            *(float4*)&a[4] = *(float4*)&sA[kk * SA_STRIDE + rowbase + 4];
            *(float4*)&b[0] = *(float4*)&sB[kk * BN + colbase];
            *(float4*)&b[4] = *(float4*)&sB[kk * BN + colbase + 4];
#pragma unroll
            for (int i = 0; i < 8; i++)
#pragma unroll
                for (int j = 0; j < 8; j++)
                    acc[i][j] += a[i] * b[j];
        }
        __syncthreads();
    }
}

// ---------------------------------------------------------------------------
// Kernel 1: fused QKV projection.  N-tiles: [0..16)=Q heads, [16..20)=K, [20..24)=V
// ---------------------------------------------------------------------------
__global__ __launch_bounds__(256, 2)
void qkv_kernel(const float* __restrict__ x,
                const float* __restrict__ Wq,
                const float* __restrict__ Wk,
                const float* __restrict__ Wv)
{
    const int nt = blockIdx.x;
    const int m0 = blockIdx.y * BM;

    const float* Bm;
    int ldb, h, heads;
    float* dst;
    if (nt < 16)      { Bm = Wq + nt * ND;        ldb = NH * ND;   dst = g_Q; h = nt;      heads = NH;   }
    else if (nt < 20) { Bm = Wk + (nt - 16) * ND; ldb = NKVH * ND; dst = g_K; h = nt - 16; heads = NKVH; }
    else              { Bm = Wv + (nt - 20) * ND; ldb = NKVH * ND; dst = g_V; h = nt - 20; heads = NKVH; }

    float acc[8][8];
    gemm128(x + (size_t)m0 * NHID, NHID, Bm, ldb, NHID, acc);

    const int tid = threadIdx.x;
    const int rowbase = (tid >> 4) << 3;
    const int colbase = (tid & 15) << 3;
#pragma unroll
    for (int i = 0; i < 8; i++) {
        int m = m0 + rowbase + i;
        int b = m >> 11;          // /2048
        int t = m & 2047;
        float* p = dst + (((size_t)(b * heads + h) * NT + t) * ND + colbase);
        float4 v0 = make_float4(acc[i][0], acc[i][1], acc[i][2], acc[i][3]);
        float4 v1 = make_float4(acc[i][4], acc[i][5], acc[i][6], acc[i][7]);
        *(float4*)(p)     = v0;
        *(float4*)(p + 4) = v1;
    }
}

// ---------------------------------------------------------------------------
// Kernel 2: RoPE on Q and K (in place)
// ---------------------------------------------------------------------------
__global__ __launch_bounds__(256)
void rope_kernel(const float* __restrict__ cosT, const float* __restrict__ sinT)
{
    const int NQ = NB * NH * NT * (ND / 2);    // 4,194,304
    const int NK = NB * NKVH * NT * (ND / 2);  // 1,048,576
    int idx = blockIdx.x * blockDim.x + threadIdx.x;
    if (idx >= NQ + NK) return;

    float* base;
    int d2, t;
    if (idx < NQ) {
        d2 = idx & 63;
        t  = (idx >> 6) & (NT - 1);
        int bh = idx >> 17;                    // 0..31
        base = g_Q + ((size_t)bh * NT + t) * ND;
    } else {
        int k = idx - NQ;
        d2 = k & 63;
        t  = (k >> 6) & (NT - 1);
        int bh = k >> 17;                      // 0..7
        base = g_K + ((size_t)bh * NT + t) * ND;
    }
    float v1 = base[d2];
    float v2 = base[d2 + 64];
    float c1 = cosT[t * ND + d2],      s1 = sinT[t * ND + d2];
    float c2 = cosT[t * ND + d2 + 64], s2 = sinT[t * ND + d2 + 64];
    base[d2]      = v1 * c1 - v2 * s1;
    base[d2 + 64] = v2 * c2 + v1 * s2;
}

// ---------------------------------------------------------------------------
// Kernel 3: causal flash attention (fp32, online softmax)
// 64 q-rows x 64 k-cols tiles, 256 threads = 16x16 thread grid
// ---------------------------------------------------------------------------
#define QT 64
#define KT 64
#define SMEM_ATTN ((ND*QT + ND*KT + KT*ND + KT*QT) * 4)   // 114688 bytes

__global__ __launch_bounds__(256, 2)
void attn_kernel()
{
    extern __shared__ float sm[];
    float* sQ = sm;                 // [d][r]  128x64
    float* sK = sQ + ND * QT;       // [d][c]  128x64
    float* sV = sK + ND * KT;       // [j][d]   64x128
    float* sP = sV + KT * ND;       // [c][r]   64x64  (P transposed)

    const int qi = gridDim.x - 1 - blockIdx.x;   // big tiles launch first
    const int h  = blockIdx.y;
    const int b  = blockIdx.z;
    const int kvh = h >> 2;
    const int q0 = qi * QT;

    const int tid = threadIdx.x;
    const int ty = tid >> 4, tx = tid & 15;
    const int r0  = ty * 4;        // S/O row base
    const int c0s = tx * 4;        // S col base
    const int c0v = tx * 8;        // O col base
    const float scale = 0.08838834764831845f;   // 1/sqrt(128)
    const float NEG = -1e30f;

    const float* Qg  = g_Q + ((size_t)(b * NH + h) * NT + q0) * ND;
    const float* Kg0 = g_K + ((size_t)(b * NKVH + kvh) * NT) * ND;
    const float* Vg0 = g_V + ((size_t)(b * NKVH + kvh) * NT) * ND;

    // Load Q tile transposed + pre-scaled
#pragma unroll
    for (int tti = 0; tti < 8; tti++) {
        int i = tid + tti * 256;          // 2048 float4s
        int r  = i >> 5;                  // 0..63
        int dd = (i & 31) << 2;           // 0..124
        float4 v = *(const float4*)(Qg + (size_t)r * ND + dd);
        sQ[(dd + 0) * QT + r] = v.x * scale;
        sQ[(dd + 1) * QT + r] = v.y * scale;
        sQ[(dd + 2) * QT + r] = v.z * scale;
        sQ[(dd + 3) * QT + r] = v.w * scale;
    }

    float o[4][8];
#pragma unroll
    for (int i = 0; i < 4; i++)
#pragma unroll
        for (int c = 0; c < 8; c++) o[i][c] = 0.0f;
    float mrow[4] = {NEG, NEG, NEG, NEG};
    float lrow[4] = {0.f, 0.f, 0.f, 0.f};

    for (int kt = 0; kt <= qi; kt++) {
        const int k0 = kt * KT;
        __syncthreads();   // previous PV done before overwriting sK/sV/sP

        const float* Kg = Kg0 + (size_t)k0 * ND;
        const float* Vg = Vg0 + (size_t)k0 * ND;
#pragma unroll
        for (int tti = 0; tti < 8; tti++) {
            int i = tid + tti * 256;
            int r  = i >> 5;
            int dd = (i & 31) << 2;
            float4 kv = *(const float4*)(Kg + (size_t)r * ND + dd);
            sK[(dd + 0) * KT + r] = kv.x;
            sK[(dd + 1) * KT + r] = kv.y;
            sK[(dd + 2) * KT + r] = kv.z;
            sK[(dd + 3) * KT + r] = kv.w;
            *(float4*)&sV[r * ND + dd] = *(const float4*)(Vg + (size_t)r * ND + dd);
        }
        __syncthreads();

        // S = Q K^T (pre-scaled)
        float s4[4][4];
#pragma unroll
        for (int i = 0; i < 4; i++)
#pragma unroll
            for (int j = 0; j < 4; j++) s4[i][j] = 0.0f;

#pragma unroll 4
        for (int d = 0; d < ND; d++) {
            float4 qa = *(float4*)&sQ[d * QT + r0];
            float4 kb = *(float4*)&sK[d * KT + c0s];
            float qv[4] = {qa.x, qa.y, qa.z, qa.w};
            float kv[4] = {kb.x, kb.y, kb.z, kb.w};
#pragma unroll
            for (int i = 0; i < 4; i++)
#pragma unroll
                for (int j = 0; j < 4; j++)
                    s4[i][j] += qv[i] * kv[j];
        }

        // Causal mask (only the diagonal tile: k0 == q0 there)
        if (kt == qi) {
#pragma unroll
            for (int i = 0; i < 4; i++)
#pragma unroll
                for (int j = 0; j < 4; j++)
                    if (c0s + j > r0 + i) s4[i][j] = NEG;
        }

        // Online softmax update (rows spread across 16 tx lanes; width-16 shfl)
#pragma unroll
        for (int i = 0; i < 4; i++) {
            float rm = fmaxf(fmaxf(s4[i][0], s4[i][1]), fmaxf(s4[i][2], s4[i][3]));
#pragma unroll
            for (int off = 8; off > 0; off >>= 1)
                rm = fmaxf(rm, __shfl_xor_sync(0xffffffffu, rm, off, 16));
            float mn = fmaxf(mrow[i], rm);
            float alpha = __expf(mrow[i] - mn);
            float rs = 0.0f;
#pragma unroll
            for (int j = 0; j < 4; j++) {
                float p = __expf(s4[i][j] - mn);
                s4[i][j] = p;
                rs += p;
            }
#pragma unroll
            for (int off = 8; off > 0; off >>= 1)
                rs += __shfl_xor_sync(0xffffffffu, rs, off, 16);
            lrow[i] = lrow[i] * alpha + rs;
            mrow[i] = mn;
#pragma unroll
            for (int c = 0; c < 8; c++) o[i][c] *= alpha;
        }

        // Store P transposed: sP[c][r]
#pragma unroll
        for (int i = 0; i < 4; i++)
#pragma unroll
            for (int j = 0; j < 4; j++)
                sP[(c0s + j) * QT + (r0 + i)] = s4[i][j];
        __syncthreads();

        // O += P @ V
#pragma unroll 4
        for (int j = 0; j < KT; j++) {
            float4 pa = *(float4*)&sP[j * QT + r0];
            float4 va = *(float4*)&sV[j * ND + c0v];
            float4 vb = *(float4*)&sV[j * ND + c0v + 4];
            float pv[4] = {pa.x, pa.y, pa.z, pa.w};
            float vv[8] = {va.x, va.y, va.z, va.w, vb.x, vb.y, vb.z, vb.w};
#pragma unroll
            for (int i = 0; i < 4; i++)
#pragma unroll
                for (int c = 0; c < 8; c++)
                    o[i][c] += pv[i] * vv[c];
        }
    }

    // Epilogue: normalize and write to g_A [B,T,H*D]
#pragma unroll
    for (int i = 0; i < 4; i++) {
        float inv = 1.0f / lrow[i];
        size_t row = (size_t)(b * NT + q0 + r0 + i);
        float* p = g_A + row * (NH * ND) + h * ND + c0v;
        float4 v0 = make_float4(o[i][0] * inv, o[i][1] * inv, o[i][2] * inv, o[i][3] * inv);
        float4 v1 = make_float4(o[i][4] * inv, o[i][5] * inv, o[i][6] * inv, o[i][7] * inv);
        *(float4*)(p)     = v0;
        *(float4*)(p + 4) = v1;
    }
}

// ---------------------------------------------------------------------------
// Kernel 4: output projection  out = g_A @ Wo
// ---------------------------------------------------------------------------
__global__ __launch_bounds__(256, 2)
void oproj_kernel(const float* __restrict__ Wo, float* __restrict__ out)
{
    const int n0 = blockIdx.x * BN;
    const int m0 = blockIdx.y * BM;

    float acc[8][8];
    gemm128(g_A + (size_t)m0 * (NH * ND), NH * ND, Wo + n0, NHID, NH * ND, acc);

    const int tid = threadIdx.x;
    const int rowbase = (tid >> 4) << 3;
    const int colbase = (tid & 15) << 3;
#pragma unroll
    for (int i = 0; i < 8; i++) {
        float* p = out + (size_t)(m0 + rowbase + i) * NHID + n0 + colbase;
        float4 v0 = make_float4(acc[i][0], acc[i][1], acc[i][2], acc[i][3]);
        float4 v1 = make_float4(acc[i][4], acc[i][5], acc[i][6], acc[i][7]);
        *(float4*)(p)     = v0;
        *(float4*)(p + 4) = v1;
    }
}

// ---------------------------------------------------------------------------
extern "C" void kernel_launch(void* const* d_in, const int* in_sizes, int n_in,
                              void* d_out, int out_size)
{
    const float* x  = (const float*)d_in[0];
    const float* rc = (const float*)d_in[1];
    const float* rs = (const float*)d_in[2];
    const float* Wq = (const float*)d_in[3];
    const float* Wk = (const float*)d_in[4];
    const float* Wv = (const float*)d_in[5];
    const float* Wo = (const float*)d_in[6];
    float* out = (float*)d_out;

    // Not a stream op; safe (and idempotent) during graph capture.
    cudaFuncSetAttribute(attn_kernel,
                         cudaFuncAttributeMaxDynamicSharedMemorySize, SMEM_ATTN);

    qkv_kernel<<<dim3(24, NM / BM), 256>>>(x, Wq, Wk, Wv);

    const int npair = NB * NH * NT * (ND / 2) + NB * NKVH * NT * (ND / 2);
    rope_kernel<<<(npair + 255) / 256, 256>>>(rc, rs);

    attn_kernel<<<dim3(NT / QT, NH, NB), 256, SMEM_ATTN>>>();

    oproj_kernel<<<dim3(NHID / BN, NM / BM), 256>>>(Wo, out);
}

// round 17
// speedup vs baseline: 1.0042x; 1.0042x over previous
#include <cuda_runtime.h>
#include <math.h>

// Problem dims
#define NB   2
#define NT   2048
#define NHID 2048
#define NH   16
#define NKVH 4
#define ND   128
#define NM   (NB*NT)      // 4096 rows

// Scratch (device globals: allocation-free)
__device__ float g_Q[(size_t)NB*NH*NT*ND];    // [B,H,T,D]   32MB
__device__ float g_K[(size_t)NB*NKVH*NT*ND];  // [B,KVH,T,D]  8MB
__device__ float g_V[(size_t)NB*NKVH*NT*ND];  //              8MB
__device__ float g_A[(size_t)NB*NT*NH*ND];    // attn out [B,T,H*D] 32MB

// ---------------------------------------------------------------------------
// SGEMM core: 128x128 tile, K-step 16, 256 threads, 8x8 micro-tile
// ---------------------------------------------------------------------------
#define BM 128
#define BN 128
#define BK 16
#define SA_STRIDE 132   // padded to break store bank conflicts

__device__ __forceinline__ void gemm128(const float* __restrict__ A, int lda,
                                        const float* __restrict__ Bm, int ldb,
                                        int K, float acc[8][8])
{
    __shared__ float sA[BK * SA_STRIDE];   // transposed: sA[k][m]
    __shared__ float sB[BK * BN];          // sB[k][n]
    const int tid = threadIdx.x;
    const int rowbase = (tid >> 4) << 3;
    const int colbase = (tid & 15) << 3;

#pragma unroll
    for (int i = 0; i < 8; i++)
#pragma unroll
        for (int j = 0; j < 8; j++) acc[i][j] = 0.0f;

    for (int kt = 0; kt < K; kt += BK) {
        // Load A tile (128x16) transposed into sA
#pragma unroll
        for (int t = 0; t < 2; t++) {
            int i = tid * 2 + t;              // 0..511 float4s
            int r  = i >> 2;                  // row 0..127
            int cg = (i & 3) << 2;            // col 0,4,8,12
            float4 v = *(const float4*)(A + (size_t)r * lda + kt + cg);
            sA[(cg + 0) * SA_STRIDE + r] = v.x;
            sA[(cg + 1) * SA_STRIDE + r] = v.y;
            sA[(cg + 2) * SA_STRIDE + r] = v.z;
            sA[(cg + 3) * SA_STRIDE + r] = v.w;
        }
        // Load B tile (16x128)
#pragma unroll
        for (int t = 0; t < 2; t++) {
            int i = tid * 2 + t;
            int r = i >> 5;                   // row 0..15
            int c = (i & 31) << 2;            // col 0..124
            *(float4*)&sB[r * BN + c] =
                *(const float4*)(Bm + (size_t)(kt + r) * ldb + c);
        }
        __syncthreads();

#pragma unroll
        for (int kk = 0; kk < BK; kk++) {
            float a[8], b[8];
            *(float4*)&a[0] = *(float4*)&sA[kk * SA_STRIDE + rowbase];
            *(float4*)&a[4] = *(float4*)&sA[kk * SA_STRIDE + rowbase + 4];
            *(float4*)&b[0] = *(float4*)&sB[kk * BN + colbase];
            *(float4*)&b[4] = *(float4*)&sB[kk * BN + colbase + 4];
#pragma unroll
            for (int i = 0; i < 8; i++)
#pragma unroll
                for (int j = 0; j < 8; j++)
                    acc[i][j] += a[i] * b[j];
        }
        __syncthreads();
    }
}

// ---------------------------------------------------------------------------
// Kernel 1: fused QKV projection.  N-tiles: [0..16)=Q heads, [16..20)=K, [20..24)=V
// ---------------------------------------------------------------------------
__global__ __launch_bounds__(256, 2)
void qkv_kernel(const float* __restrict__ x,
                const float* __restrict__ Wq,
                const float* __restrict__ Wk,
                const float* __restrict__ Wv)
{
    const int nt = blockIdx.x;
    const int m0 = blockIdx.y * BM;

    const float* Bm;
    int ldb, h, heads;
    float* dst;
    if (nt < 16)      { Bm = Wq + nt * ND;        ldb = NH * ND;   dst = g_Q; h = nt;      heads = NH;   }
    else if (nt < 20) { Bm = Wk + (nt - 16) * ND; ldb = NKVH * ND; dst = g_K; h = nt - 16; heads = NKVH; }
    else              { Bm = Wv + (nt - 20) * ND; ldb = NKVH * ND; dst = g_V; h = nt - 20; heads = NKVH; }

    float acc[8][8];
    gemm128(x + (size_t)m0 * NHID, NHID, Bm, ldb, NHID, acc);

    const int tid = threadIdx.x;
    const int rowbase = (tid >> 4) << 3;
    const int colbase = (tid & 15) << 3;
#pragma unroll
    for (int i = 0; i < 8; i++) {
        int m = m0 + rowbase + i;
        int b = m >> 11;          // /2048
        int t = m & 2047;
        float* p = dst + (((size_t)(b * heads + h) * NT + t) * ND + colbase);
        float4 v0 = make_float4(acc[i][0], acc[i][1], acc[i][2], acc[i][3]);
        float4 v1 = make_float4(acc[i][4], acc[i][5], acc[i][6], acc[i][7]);
        *(float4*)(p)     = v0;
        *(float4*)(p + 4) = v1;
    }
}

// ---------------------------------------------------------------------------
// Kernel 2: RoPE on Q and K (in place)
// ---------------------------------------------------------------------------
__global__ __launch_bounds__(256)
void rope_kernel(const float* __restrict__ cosT, const float* __restrict__ sinT)
{
    const int NQ = NB * NH * NT * (ND / 2);    // 4,194,304
    const int NK = NB * NKVH * NT * (ND / 2);  // 1,048,576
    int idx = blockIdx.x * blockDim.x + threadIdx.x;
    if (idx >= NQ + NK) return;

    float* base;
    int d2, t;
    if (idx < NQ) {
        d2 = idx & 63;
        t  = (idx >> 6) & (NT - 1);
        int bh = idx >> 17;                    // 0..31
        base = g_Q + ((size_t)bh * NT + t) * ND;
    } else {
        int k = idx - NQ;
        d2 = k & 63;
        t  = (k >> 6) & (NT - 1);
        int bh = k >> 17;                      // 0..7
        base = g_K + ((size_t)bh * NT + t) * ND;
    }
    float v1 = base[d2];
    float v2 = base[d2 + 64];
    float c1 = cosT[t * ND + d2],      s1 = sinT[t * ND + d2];
    float c2 = cosT[t * ND + d2 + 64], s2 = sinT[t * ND + d2 + 64];
    base[d2]      = v1 * c1 - v2 * s1;
    base[d2 + 64] = v2 * c2 + v1 * s2;
}

// ---------------------------------------------------------------------------
// Kernel 3: causal flash attention (fp32, online softmax)
// 64 q-rows x 64 k-cols tiles, 256 threads = 16x16 thread grid
// ---------------------------------------------------------------------------
#define QT 64
#define KT 64
#define SMEM_ATTN ((ND*QT + ND*KT + KT*ND + KT*QT) * 4)   // 114688 bytes

__global__ __launch_bounds__(256, 2)
void attn_kernel()
{
    extern __shared__ float sm[];
    float* sQ = sm;                 // [d][r]  128x64
    float* sK = sQ + ND * QT;       // [d][c]  128x64
    float* sV = sK + ND * KT;       // [j][d]   64x128
    float* sP = sV + KT * ND;       // [c][r]   64x64  (P transposed)

    const int qi = gridDim.x - 1 - blockIdx.x;   // big tiles launch first
    const int h  = blockIdx.y;
    const int b  = blockIdx.z;
    const int kvh = h >> 2;
    const int q0 = qi * QT;

    const int tid = threadIdx.x;
    const int ty = tid >> 4, tx = tid & 15;
    const int r0  = ty * 4;        // S/O row base
    const int c0s = tx * 4;        // S col base
    const int c0v = tx * 8;        // O col base
    const float scale = 0.08838834764831845f;   // 1/sqrt(128)
    const float NEG = -1e30f;

    const float* Qg  = g_Q + ((size_t)(b * NH + h) * NT + q0) * ND;
    const float* Kg0 = g_K + ((size_t)(b * NKVH + kvh) * NT) * ND;
    const float* Vg0 = g_V + ((size_t)(b * NKVH + kvh) * NT) * ND;

    // Load Q tile transposed + pre-scaled
#pragma unroll
    for (int tti = 0; tti < 8; tti++) {
        int i = tid + tti * 256;          // 2048 float4s
        int r  = i >> 5;                  // 0..63
        int dd = (i & 31) << 2;           // 0..124
        float4 v = *(const float4*)(Qg + (size_t)r * ND + dd);
        sQ[(dd + 0) * QT + r] = v.x * scale;
        sQ[(dd + 1) * QT + r] = v.y * scale;
        sQ[(dd + 2) * QT + r] = v.z * scale;
        sQ[(dd + 3) * QT + r] = v.w * scale;
    }

    float o[4][8];
#pragma unroll
    for (int i = 0; i < 4; i++)
#pragma unroll
        for (int c = 0; c < 8; c++) o[i][c] = 0.0f;
    float mrow[4] = {NEG, NEG, NEG, NEG};
    float lrow[4] = {0.f, 0.f, 0.f, 0.f};

    for (int kt = 0; kt <= qi; kt++) {
        const int k0 = kt * KT;
        __syncthreads();   // previous PV done before overwriting sK/sV/sP

        const float* Kg = Kg0 + (size_t)k0 * ND;
        const float* Vg = Vg0 + (size_t)k0 * ND;
#pragma unroll
        for (int tti = 0; tti < 8; tti++) {
            int i = tid + tti * 256;
            int r  = i >> 5;
            int dd = (i & 31) << 2;
            float4 kv = *(const float4*)(Kg + (size_t)r * ND + dd);
            sK[(dd + 0) * KT + r] = kv.x;
            sK[(dd + 1) * KT + r] = kv.y;
            sK[(dd + 2) * KT + r] = kv.z;
            sK[(dd + 3) * KT + r] = kv.w;
            *(float4*)&sV[r * ND + dd] = *(const float4*)(Vg + (size_t)r * ND + dd);
        }
        __syncthreads();

        // S = Q K^T (pre-scaled)
        float s4[4][4];
#pragma unroll
        for (int i = 0; i < 4; i++)
#pragma unroll
            for (int j = 0; j < 4; j++) s4[i][j] = 0.0f;

#pragma unroll 4
        for (int d = 0; d < ND; d++) {
            float4 qa = *(float4*)&sQ[d * QT + r0];
            float4 kb = *(float4*)&sK[d * KT + c0s];
            float qv[4] = {qa.x, qa.y, qa.z, qa.w};
            float kv[4] = {kb.x, kb.y, kb.z, kb.w};
#pragma unroll
            for (int i = 0; i < 4; i++)
#pragma unroll
                for (int j = 0; j < 4; j++)
                    s4[i][j] += qv[i] * kv[j];
        }

        // Causal mask (only the diagonal tile: k0 == q0 there)
        if (kt == qi) {
#pragma unroll
            for (int i = 0; i < 4; i++)
#pragma unroll
                for (int j = 0; j < 4; j++)
                    if (c0s + j > r0 + i) s4[i][j] = NEG;
        }

        // Online softmax update (rows spread across 16 tx lanes; width-16 shfl)
#pragma unroll
        for (int i = 0; i < 4; i++) {
            float rm = fmaxf(fmaxf(s4[i][0], s4[i][1]), fmaxf(s4[i][2], s4[i][3]));
#pragma unroll
            for (int off = 8; off > 0; off >>= 1)
                rm = fmaxf(rm, __shfl_xor_sync(0xffffffffu, rm, off, 16));
            float mn = fmaxf(mrow[i], rm);
            float alpha = __expf(mrow[i] - mn);
            float rs = 0.0f;
#pragma unroll
            for (int j = 0; j < 4; j++) {
                float p = __expf(s4[i][j] - mn);
                s4[i][j] = p;
                rs += p;
            }
#pragma unroll
            for (int off = 8; off > 0; off >>= 1)
                rs += __shfl_xor_sync(0xffffffffu, rs, off, 16);
            lrow[i] = lrow[i] * alpha + rs;
            mrow[i] = mn;
#pragma unroll
            for (int c = 0; c < 8; c++) o[i][c] *= alpha;
        }

        // Store P transposed: sP[c][r]
#pragma unroll
        for (int i = 0; i < 4; i++)
#pragma unroll
            for (int j = 0; j < 4; j++)
                sP[(c0s + j) * QT + (r0 + i)] = s4[i][j];
        __syncthreads();

        // O += P @ V
#pragma unroll 4
        for (int j = 0; j < KT; j++) {
            float4 pa = *(float4*)&sP[j * QT + r0];
            float4 va = *(float4*)&sV[j * ND + c0v];
            float4 vb = *(float4*)&sV[j * ND + c0v + 4];
            float pv[4] = {pa.x, pa.y, pa.z, pa.w};
            float vv[8] = {va.x, va.y, va.z, va.w, vb.x, vb.y, vb.z, vb.w};
#pragma unroll
            for (int i = 0; i < 4; i++)
#pragma unroll
                for (int c = 0; c < 8; c++)
                    o[i][c] += pv[i] * vv[c];
        }
    }

    // Epilogue: normalize and write to g_A [B,T,H*D]
#pragma unroll
    for (int i = 0; i < 4; i++) {
        float inv = 1.0f / lrow[i];
        size_t row = (size_t)(b * NT + q0 + r0 + i);
        float* p = g_A + row * (NH * ND) + h * ND + c0v;
        float4 v0 = make_float4(o[i][0] * inv, o[i][1] * inv, o[i][2] * inv, o[i][3] * inv);
        float4 v1 = make_float4(o[i][4] * inv, o[i][5] * inv, o[i][6] * inv, o[i][7] * inv);
        *(float4*)(p)     = v0;
        *(float4*)(p + 4) = v1;
    }
}

// ---------------------------------------------------------------------------
// Kernel 4: output projection  out = g_A @ Wo
// ---------------------------------------------------------------------------
__global__ __launch_bounds__(256, 2)
void oproj_kernel(const float* __restrict__ Wo, float* __restrict__ out)
{
    const int n0 = blockIdx.x * BN;
    const int m0 = blockIdx.y * BM;

    float acc[8][8];
    gemm128(g_A + (size_t)m0 * (NH * ND), NH * ND, Wo + n0, NHID, NH * ND, acc);

    const int tid = threadIdx.x;
    const int rowbase = (tid >> 4) << 3;
    const int colbase = (tid & 15) << 3;
#pragma unroll
    for (int i = 0; i < 8; i++) {
        float* p = out + (size_t)(m0 + rowbase + i) * NHID + n0 + colbase;
        float4 v0 = make_float4(acc[i][0], acc[i][1], acc[i][2], acc[i][3]);
        float4 v1 = make_float4(acc[i][4], acc[i][5], acc[i][6], acc[i][7]);
        *(float4*)(p)     = v0;
        *(float4*)(p + 4) = v1;
    }
}

// ---------------------------------------------------------------------------
extern "C" void kernel_launch(void* const* d_in, const int* in_sizes, int n_in,
                              void* d_out, int out_size)
{
    const float* x  = (const float*)d_in[0];
    const float* rc = (const float*)d_in[1];
    const float* rs = (const float*)d_in[2];
    const float* Wq = (const float*)d_in[3];
    const float* Wk = (const float*)d_in[4];
    const float* Wv = (const float*)d_in[5];
    const float* Wo = (const float*)d_in[6];
    float* out = (float*)d_out;

    // Not a stream op; safe (and idempotent) during graph capture.
    cudaFuncSetAttribute(attn_kernel,
                         cudaFuncAttributeMaxDynamicSharedMemorySize, SMEM_ATTN);

    qkv_kernel<<<dim3(24, NM / BM), 256>>>(x, Wq, Wk, Wv);

    const int npair = NB * NH * NT * (ND / 2) + NB * NKVH * NT * (ND / 2);
    rope_kernel<<<(npair + 255) / 256, 256>>>(rc, rs);

    attn_kernel<<<dim3(NT / QT, NH, NB), 256, SMEM_ATTN>>>();

    oproj_kernel<<<dim3(NHID / BN, NM / BM), 256>>>(Wo, out);
}